// round 3
// baseline (speedup 1.0000x reference)
#include <cuda_runtime.h>
#include <math.h>

// Scratch for fused gated features X [B*L, 768] = [32768, 768] fp32 (96 MB).
__device__ float g_X[25165824];

// ---------------------------------------------------------------------------
// Kernel 1: gated linear fusion
//   C1 = Xe @ W1^T (K=768), C2 = Xp @ W2^T (K=320)
//   A  = sigmoid(C1 + b1);  X = A*Xe + (1-A)*tanh(C2 + b2)
// Block tile 64(M) x 64(N), BK=32, 256 threads, 4x4 micro-tile.
// ---------------------------------------------------------------------------
__global__ __launch_bounds__(256) void gate_kernel(
    const float* __restrict__ Xe, const float* __restrict__ Xp,
    const float* __restrict__ W1, const float* __restrict__ b1,
    const float* __restrict__ W2, const float* __restrict__ b2)
{
    __shared__ float As[32][68];
    __shared__ float Bs[32][68];

    const int m0  = blockIdx.y * 64;
    const int n0  = blockIdx.x * 64;
    const int tid = threadIdx.x;
    const int tc  = tid & 15;   // 0..15 -> output cols tc*4..tc*4+3
    const int tr  = tid >> 4;   // 0..15 -> output rows tr*4..tr*4+3

    float acc1[4][4] = {};
    float acc2[4][4] = {};

    // ---- GEMM1: Xe (stride 768) vs W1 (stride 768), K = 768 ----
    for (int k0 = 0; k0 < 768; k0 += 32) {
        #pragma unroll
        for (int it = 0; it < 2; it++) {
            int idx = tid + it * 256;      // 0..511 float4 slots (64 rows x 8)
            int row = idx >> 3;
            int kq  = (idx & 7) << 2;
            float4 va = *(const float4*)(Xe + (size_t)(m0 + row) * 768 + k0 + kq);
            As[kq + 0][row] = va.x; As[kq + 1][row] = va.y;
            As[kq + 2][row] = va.z; As[kq + 3][row] = va.w;
            float4 vb = *(const float4*)(W1 + (size_t)(n0 + row) * 768 + k0 + kq);
            Bs[kq + 0][row] = vb.x; Bs[kq + 1][row] = vb.y;
            Bs[kq + 2][row] = vb.z; Bs[kq + 3][row] = vb.w;
        }
        __syncthreads();
        #pragma unroll
        for (int kk = 0; kk < 32; kk++) {
            float4 a = *(const float4*)&As[kk][tr * 4];
            float4 b = *(const float4*)&Bs[kk][tc * 4];
            float aa[4] = {a.x, a.y, a.z, a.w};
            float bb[4] = {b.x, b.y, b.z, b.w};
            #pragma unroll
            for (int i = 0; i < 4; i++)
                #pragma unroll
                for (int j = 0; j < 4; j++)
                    acc1[i][j] += aa[i] * bb[j];
        }
        __syncthreads();
    }

    // ---- GEMM2: Xp (stride 320) vs W2 (stride 320), K = 320 ----
    for (int k0 = 0; k0 < 320; k0 += 32) {
        #pragma unroll
        for (int it = 0; it < 2; it++) {
            int idx = tid + it * 256;
            int row = idx >> 3;
            int kq  = (idx & 7) << 2;
            float4 va = *(const float4*)(Xp + (size_t)(m0 + row) * 320 + k0 + kq);
            As[kq + 0][row] = va.x; As[kq + 1][row] = va.y;
            As[kq + 2][row] = va.z; As[kq + 3][row] = va.w;
            float4 vb = *(const float4*)(W2 + (size_t)(n0 + row) * 320 + k0 + kq);
            Bs[kq + 0][row] = vb.x; Bs[kq + 1][row] = vb.y;
            Bs[kq + 2][row] = vb.z; Bs[kq + 3][row] = vb.w;
        }
        __syncthreads();
        #pragma unroll
        for (int kk = 0; kk < 32; kk++) {
            float4 a = *(const float4*)&As[kk][tr * 4];
            float4 b = *(const float4*)&Bs[kk][tc * 4];
            float aa[4] = {a.x, a.y, a.z, a.w};
            float bb[4] = {b.x, b.y, b.z, b.w};
            #pragma unroll
            for (int i = 0; i < 4; i++)
                #pragma unroll
                for (int j = 0; j < 4; j++)
                    acc2[i][j] += aa[i] * bb[j];
        }
        __syncthreads();
    }

    // ---- epilogue: gate + mix, write fused X ----
    #pragma unroll
    for (int i = 0; i < 4; i++) {
        int m = m0 + tr * 4 + i;
        const float* xe_row = Xe + (size_t)m * 768;
        float*       xo_row = g_X + (size_t)m * 768;
        #pragma unroll
        for (int j = 0; j < 4; j++) {
            int o = n0 + tc * 4 + j;
            float g  = 1.0f / (1.0f + expf(-(acc1[i][j] + b1[o])));
            float pv = tanhf(acc2[i][j] + b2[o]);
            xo_row[o] = g * xe_row[o] + (1.0f - g) * pv;
        }
    }
}

// ---------------------------------------------------------------------------
// Kernel 2: conv1d (k=3, pad=1) as shifted GEMM + fused piecewise max-pool
//   y[b,l,o] = sum_t sum_i Wc[o,i,t] * X[b, l+t-1, i] + bc[o]
//   pooled[b,o,k] = max_l (y * (mask==k+1 ? 1 : 0));  out = tanh(pooled)
// One block = (batch b, 64 o's), persistent over all 512 L (8 chunks of 64).
// ---------------------------------------------------------------------------
__global__ __launch_bounds__(256) void conv_pool_kernel(
    const int* __restrict__ Xmask, const float* __restrict__ Wc,
    const float* __restrict__ bc, float* __restrict__ out)
{
    __shared__ float Xs[32][68];      // [kk][r1], r1=0..65 covers rows l0-1 .. l0+64
    __shared__ float Ws[32][3][68];   // [kk][tap][o-col]
    __shared__ float red[16][64];

    const int b   = blockIdx.y;
    const int o0  = blockIdx.x * 64;
    const int tid = threadIdx.x;
    const int tc  = tid & 15;
    const int tr  = tid >> 4;

    float pm[3][4];
    #pragma unroll
    for (int k = 0; k < 3; k++)
        #pragma unroll
        for (int j = 0; j < 4; j++) pm[k][j] = -INFINITY;

    float bcv[4];
    #pragma unroll
    for (int j = 0; j < 4; j++) bcv[j] = bc[o0 + tc * 4 + j];

    for (int lc = 0; lc < 8; lc++) {
        const int l0 = lc * 64;
        float acc[4][4] = {};

        for (int k0 = 0; k0 < 768; k0 += 32) {
            // X rows l0-1 .. l0+64 (66 rows) x 32 k's; zero-pad conv boundary
            for (int idx = tid; idx < 66 * 32; idx += 256) {
                int r1 = idx >> 5;
                int kk = idx & 31;
                int l  = l0 + r1 - 1;
                float v = 0.0f;
                if (l >= 0 && l < 512)
                    v = g_X[((size_t)b * 512 + l) * 768 + k0 + kk];
                Xs[kk][r1] = v;
            }
            // Wc tile: 64 o's x 32 i's x 3 taps (contiguous per-o runs of 96)
            for (int idx = tid; idx < 64 * 96; idx += 256) {
                int col = idx / 96;
                int rem = idx - col * 96;
                int kk  = rem / 3;
                int t   = rem - kk * 3;
                Ws[kk][t][col] = Wc[((size_t)(o0 + col) * 768 + (k0 + kk)) * 3 + t];
            }
            __syncthreads();
            #pragma unroll
            for (int kk = 0; kk < 32; kk++) {
                float4 a4 = *(const float4*)&Xs[kk][tr * 4];
                float av[6];
                av[0] = a4.x; av[1] = a4.y; av[2] = a4.z; av[3] = a4.w;
                av[4] = Xs[kk][tr * 4 + 4];
                av[5] = Xs[kk][tr * 4 + 5];
                #pragma unroll
                for (int t = 0; t < 3; t++) {
                    float4 b4 = *(const float4*)&Ws[kk][t][tc * 4];
                    float bb[4] = {b4.x, b4.y, b4.z, b4.w};
                    #pragma unroll
                    for (int i = 0; i < 4; i++)
                        #pragma unroll
                        for (int j = 0; j < 4; j++)
                            acc[i][j] += av[i + t] * bb[j];
                }
            }
            __syncthreads();
        }

        // fused piecewise pooling for this L-chunk (exact y*m semantics:
        // every l contributes either y or 0 to each segment)
        #pragma unroll
        for (int i = 0; i < 4; i++) {
            int l  = l0 + tr * 4 + i;
            int mk = Xmask[b * 512 + l];
            #pragma unroll
            for (int j = 0; j < 4; j++) {
                float val = acc[i][j] + bcv[j];
                #pragma unroll
                for (int k = 0; k < 3; k++) {
                    float c = (mk == k + 1) ? val : 0.0f;
                    pm[k][j] = fmaxf(pm[k][j], c);
                }
            }
        }
    }

    // reduce partial maxima across the 16 thread-rows, tanh, write out
    #pragma unroll
    for (int k = 0; k < 3; k++) {
        __syncthreads();
        #pragma unroll
        for (int j = 0; j < 4; j++) red[tr][tc * 4 + j] = pm[k][j];
        __syncthreads();
        for (int off = 8; off >= 1; off >>= 1) {
            if (tr < off) {
                #pragma unroll
                for (int j = 0; j < 4; j++) {
                    int c = tc * 4 + j;
                    red[tr][c] = fmaxf(red[tr][c], red[tr + off][c]);
                }
            }
            __syncthreads();
        }
        if (tr == 0) {
            #pragma unroll
            for (int j = 0; j < 4; j++) {
                int o = o0 + tc * 4 + j;
                out[(size_t)b * 2304 + o * 3 + k] = tanhf(red[0][tc * 4 + j]);
            }
        }
    }
}

// ---------------------------------------------------------------------------
extern "C" void kernel_launch(void* const* d_in, const int* in_sizes, int n_in,
                              void* d_out, int out_size)
{
    const float* Xp = (const float*)d_in[0];
    const float* Xe = (const float*)d_in[1];
    const int*   Xm = (const int*)  d_in[2];
    const float* W1 = (const float*)d_in[3];
    const float* b1 = (const float*)d_in[4];
    const float* W2 = (const float*)d_in[5];
    const float* b2 = (const float*)d_in[6];
    const float* Wc = (const float*)d_in[7];
    const float* bc = (const float*)d_in[8];
    float* out = (float*)d_out;

    dim3 g1(12, 512);   // 768/64 n-tiles, 32768/64 m-tiles
    gate_kernel<<<g1, 256>>>(Xe, Xp, W1, b1, W2, b2);

    dim3 g2(12, 64);    // 768/64 o-tiles, 64 batches
    conv_pool_kernel<<<g2, 256>>>(Xm, Wc, bc, out);
}

// round 4
// speedup vs baseline: 1.8571x; 1.8571x over previous
#include <cuda_runtime.h>
#include <math.h>

// Scratch: fused gated features X and raw C1, each [32768, 768] fp32 (96 MB).
__device__ float g_X[25165824];
__device__ float g_C[25165824];

typedef unsigned long long u64;

__device__ __forceinline__ u64 pk2(float x) {
    u64 r; asm("mov.b64 %0, {%1, %1};" : "=l"(r) : "f"(x)); return r;
}
__device__ __forceinline__ u64 fma2(u64 a, u64 b, u64 c) {
    u64 d; asm("fma.rn.f32x2 %0, %1, %2, %3;" : "=l"(d) : "l"(a), "l"(b), "l"(c));
    return d;
}
__device__ __forceinline__ void upk(u64 v, float& lo, float& hi) {
    asm("mov.b64 {%0, %1}, %2;" : "=f"(lo), "=f"(hi) : "l"(v));
}

// ---------------------------------------------------------------------------
// Generic 128x128 tile GEMM core: C = A[M,K] @ W[N,K]^T, BK=32, 256 threads,
// 8x8 micro-tile with packed f32x2 FMAs (acc[8][4] = 8 rows x 4 col-pairs).
// ---------------------------------------------------------------------------
template <int K>
__device__ __forceinline__ void gemm_tile(
    const float* __restrict__ A, const float* __restrict__ W,
    int m0, int n0, u64 acc[8][4],
    float (*As)[38], float (*Bs)[132])
{
    const int tid  = threadIdx.x;
    const int rowT = tid >> 4;   // 0..15 -> rows rowT*8..+7
    const int colT = tid & 15;   // 0..15 -> cols colT*8..+7

    #pragma unroll
    for (int i = 0; i < 8; i++)
        #pragma unroll
        for (int p = 0; p < 4; p++) acc[i][p] = 0ULL;

    for (int k0 = 0; k0 < K; k0 += 32) {
        #pragma unroll
        for (int it = 0; it < 4; it++) {
            int idx = tid + it * 256;           // 0..1023: 128 rows x 8 float4
            int row = idx >> 3;
            int kq  = (idx & 7) << 2;
            float4 va = *(const float4*)(A + (size_t)(m0 + row) * K + k0 + kq);
            As[row][kq + 0] = va.x; As[row][kq + 1] = va.y;
            As[row][kq + 2] = va.z; As[row][kq + 3] = va.w;
            float4 vb = *(const float4*)(W + (size_t)(n0 + row) * K + k0 + kq);
            Bs[kq + 0][row] = vb.x; Bs[kq + 1][row] = vb.y;
            Bs[kq + 2][row] = vb.z; Bs[kq + 3][row] = vb.w;
        }
        __syncthreads();
        #pragma unroll 4
        for (int kk = 0; kk < 32; kk++) {
            u64 pa[8];
            #pragma unroll
            for (int i = 0; i < 8; i++) pa[i] = pk2(As[rowT * 8 + i][kk]);
            u64 pb[4];
            #pragma unroll
            for (int p = 0; p < 4; p++)
                pb[p] = *(const u64*)&Bs[kk][colT * 8 + 2 * p];
            #pragma unroll
            for (int i = 0; i < 8; i++)
                #pragma unroll
                for (int p = 0; p < 4; p++)
                    acc[i][p] = fma2(pa[i], pb[p], acc[i][p]);
        }
        __syncthreads();
    }
}

// ---------------------------------------------------------------------------
// Kernel 1a: C1 = Xe @ W1^T  (K=768), raw store to g_C.
// ---------------------------------------------------------------------------
__global__ __launch_bounds__(256, 2) void gemm1_kernel(
    const float* __restrict__ Xe, const float* __restrict__ W1)
{
    __shared__ __align__(16) float As[128][38];
    __shared__ __align__(16) float Bs[32][132];
    const int m0 = blockIdx.y * 128;
    const int n0 = blockIdx.x * 128;
    u64 acc[8][4];
    gemm_tile<768>(Xe, W1, m0, n0, acc, As, Bs);

    const int rowT = threadIdx.x >> 4;
    const int colT = threadIdx.x & 15;
    #pragma unroll
    for (int i = 0; i < 8; i++) {
        int m = m0 + rowT * 8 + i;
        float4 o1, o2;
        upk(acc[i][0], o1.x, o1.y); upk(acc[i][1], o1.z, o1.w);
        upk(acc[i][2], o2.x, o2.y); upk(acc[i][3], o2.z, o2.w);
        float* dst = g_C + (size_t)m * 768 + n0 + colT * 8;
        *(float4*)(dst)     = o1;
        *(float4*)(dst + 4) = o2;
    }
}

// ---------------------------------------------------------------------------
// Kernel 1b: C2 = Xp @ W2^T (K=320); epilogue fuses the gate:
//   g = sigmoid(C1 + b1);  X = g*Xe + (1-g)*tanh(C2 + b2)  -> g_X
// ---------------------------------------------------------------------------
__global__ __launch_bounds__(256, 2) void gemm2_kernel(
    const float* __restrict__ Xp, const float* __restrict__ W2,
    const float* __restrict__ Xe,
    const float* __restrict__ b1, const float* __restrict__ b2)
{
    __shared__ __align__(16) float As[128][38];
    __shared__ __align__(16) float Bs[32][132];
    const int m0 = blockIdx.y * 128;
    const int n0 = blockIdx.x * 128;
    u64 acc[8][4];
    gemm_tile<320>(Xp, W2, m0, n0, acc, As, Bs);

    const int rowT = threadIdx.x >> 4;
    const int colT = threadIdx.x & 15;
    const int nb   = n0 + colT * 8;
    float4 b1a = *(const float4*)(b1 + nb), b1b = *(const float4*)(b1 + nb + 4);
    float4 b2a = *(const float4*)(b2 + nb), b2b = *(const float4*)(b2 + nb + 4);
    float b1v[8] = {b1a.x, b1a.y, b1a.z, b1a.w, b1b.x, b1b.y, b1b.z, b1b.w};
    float b2v[8] = {b2a.x, b2a.y, b2a.z, b2a.w, b2b.x, b2b.y, b2b.z, b2b.w};

    #pragma unroll
    for (int i = 0; i < 8; i++) {
        int m = m0 + rowT * 8 + i;
        size_t base = (size_t)m * 768 + nb;
        float4 c1a = *(const float4*)(g_C + base);
        float4 c1b = *(const float4*)(g_C + base + 4);
        float4 xea = *(const float4*)(Xe + base);
        float4 xeb = *(const float4*)(Xe + base + 4);
        float c1v[8] = {c1a.x, c1a.y, c1a.z, c1a.w, c1b.x, c1b.y, c1b.z, c1b.w};
        float xev[8] = {xea.x, xea.y, xea.z, xea.w, xeb.x, xeb.y, xeb.z, xeb.w};
        float c2v[8];
        upk(acc[i][0], c2v[0], c2v[1]); upk(acc[i][1], c2v[2], c2v[3]);
        upk(acc[i][2], c2v[4], c2v[5]); upk(acc[i][3], c2v[6], c2v[7]);
        float xv[8];
        #pragma unroll
        for (int j = 0; j < 8; j++) {
            float g  = 1.0f / (1.0f + expf(-(c1v[j] + b1v[j])));
            float pv = tanhf(c2v[j] + b2v[j]);
            xv[j] = g * xev[j] + (1.0f - g) * pv;
        }
        float4 o1 = {xv[0], xv[1], xv[2], xv[3]};
        float4 o2 = {xv[4], xv[5], xv[6], xv[7]};
        *(float4*)(g_X + base)     = o1;
        *(float4*)(g_X + base + 4) = o2;
    }
}

// ---------------------------------------------------------------------------
// Kernel 2: conv1d (k=3, pad=1) as shifted GEMM + fused piecewise max-pool.
// Block = (batch b, 64 o's), persistent over 512 L as 4 chunks of 128.
// 256 threads: 16 rowT x 16 colT, micro-tile 8 L-rows x 4 O-cols (2 f32x2).
// 3 conv taps reuse the A fragment (10 a-values per kk -> 48 FMA2).
// ---------------------------------------------------------------------------
__global__ __launch_bounds__(256, 2) void conv_pool_kernel(
    const int* __restrict__ Xmask, const float* __restrict__ Wc,
    const float* __restrict__ bc, float* __restrict__ out)
{
    __shared__ __align__(16) float Xs[130][38];     // rows l0-1 .. l0+128
    __shared__ __align__(16) float Ws[32][3][66];   // [kk][tap][o]

    const int b    = blockIdx.y;
    const int o0   = blockIdx.x * 64;
    const int tid  = threadIdx.x;
    const int rowT = tid >> 4;
    const int colT = tid & 15;

    float pm[3][4];
    #pragma unroll
    for (int k = 0; k < 3; k++)
        #pragma unroll
        for (int j = 0; j < 4; j++) pm[k][j] = -INFINITY;

    float bcv[4];
    #pragma unroll
    for (int j = 0; j < 4; j++) bcv[j] = bc[o0 + colT * 4 + j];

    for (int lc = 0; lc < 4; lc++) {
        const int l0 = lc * 128;
        u64 acc[8][2];
        #pragma unroll
        for (int i = 0; i < 8; i++) { acc[i][0] = 0ULL; acc[i][1] = 0ULL; }

        for (int k0 = 0; k0 < 768; k0 += 32) {
            // X rows l0-1 .. l0+128 (130) x 32 k's, zero-padded boundaries
            for (int idx = tid; idx < 130 * 8; idx += 256) {
                int r1 = idx >> 3;
                int kq = (idx & 7) << 2;
                int l  = l0 + r1 - 1;
                float4 v = {0.f, 0.f, 0.f, 0.f};
                if (l >= 0 && l < 512)
                    v = *(const float4*)(g_X + ((size_t)b * 512 + l) * 768 + k0 + kq);
                Xs[r1][kq + 0] = v.x; Xs[r1][kq + 1] = v.y;
                Xs[r1][kq + 2] = v.z; Xs[r1][kq + 3] = v.w;
            }
            // Wc tile: 64 o's x (32 i's x 3 taps) = 96 contiguous floats per o
            for (int idx = tid; idx < 1536; idx += 256) {
                int o = idx / 24;
                int q = idx - o * 24;
                float4 v = *(const float4*)(Wc + ((size_t)(o0 + o) * 768 + k0) * 3 + q * 4);
                int f = q * 4;
                Ws[(f + 0) / 3][(f + 0) % 3][o] = v.x;
                Ws[(f + 1) / 3][(f + 1) % 3][o] = v.y;
                Ws[(f + 2) / 3][(f + 2) % 3][o] = v.z;
                Ws[(f + 3) / 3][(f + 3) % 3][o] = v.w;
            }
            __syncthreads();
            #pragma unroll 2
            for (int kk = 0; kk < 32; kk++) {
                u64 pa[10];
                #pragma unroll
                for (int ii = 0; ii < 10; ii++)
                    pa[ii] = pk2(Xs[rowT * 8 + ii][kk]);
                #pragma unroll
                for (int t = 0; t < 3; t++) {
                    u64 pb0 = *(const u64*)&Ws[kk][t][colT * 4];
                    u64 pb1 = *(const u64*)&Ws[kk][t][colT * 4 + 2];
                    #pragma unroll
                    for (int i = 0; i < 8; i++) {
                        acc[i][0] = fma2(pa[i + t], pb0, acc[i][0]);
                        acc[i][1] = fma2(pa[i + t], pb1, acc[i][1]);
                    }
                }
            }
            __syncthreads();
        }

        // fused piecewise pooling for this L-chunk
        #pragma unroll
        for (int i = 0; i < 8; i++) {
            int l  = l0 + rowT * 8 + i;
            int mk = Xmask[b * 512 + l];
            float v[4];
            upk(acc[i][0], v[0], v[1]);
            upk(acc[i][1], v[2], v[3]);
            #pragma unroll
            for (int j = 0; j < 4; j++) {
                float val = v[j] + bcv[j];
                #pragma unroll
                for (int k = 0; k < 3; k++) {
                    float c = (mk == k + 1) ? val : 0.0f;
                    pm[k][j] = fmaxf(pm[k][j], c);
                }
            }
        }
    }

    // reduce partial maxima across the 16 thread-rows (reuse Xs as scratch)
    float (*red)[64] = (float (*)[64])Xs;
    #pragma unroll
    for (int k = 0; k < 3; k++) {
        __syncthreads();
        #pragma unroll
        for (int j = 0; j < 4; j++) red[rowT][colT * 4 + j] = pm[k][j];
        __syncthreads();
        for (int off = 8; off >= 1; off >>= 1) {
            if (rowT < off) {
                #pragma unroll
                for (int j = 0; j < 4; j++) {
                    int c = colT * 4 + j;
                    red[rowT][c] = fmaxf(red[rowT][c], red[rowT + off][c]);
                }
            }
            __syncthreads();
        }
        if (rowT == 0) {
            #pragma unroll
            for (int j = 0; j < 4; j++) {
                int o = o0 + colT * 4 + j;
                out[(size_t)b * 2304 + o * 3 + k] = tanhf(red[0][colT * 4 + j]);
            }
        }
    }
}

// ---------------------------------------------------------------------------
extern "C" void kernel_launch(void* const* d_in, const int* in_sizes, int n_in,
                              void* d_out, int out_size)
{
    const float* Xp = (const float*)d_in[0];
    const float* Xe = (const float*)d_in[1];
    const int*   Xm = (const int*)  d_in[2];
    const float* W1 = (const float*)d_in[3];
    const float* b1 = (const float*)d_in[4];
    const float* W2 = (const float*)d_in[5];
    const float* b2 = (const float*)d_in[6];
    const float* Wc = (const float*)d_in[7];
    const float* bc = (const float*)d_in[8];
    float* out = (float*)d_out;

    dim3 g1(6, 256);    // 768/128 n-tiles, 32768/128 m-tiles
    gemm1_kernel<<<g1, 256>>>(Xe, W1);
    gemm2_kernel<<<g1, 256>>>(Xp, W2, Xe, b1, b2);

    dim3 g2(12, 64);    // 768/64 o-tiles, 64 batches
    conv_pool_kernel<<<g2, 256>>>(Xm, Wc, bc, out);
}

// round 7
// speedup vs baseline: 6.3584x; 3.4239x over previous
#include <cuda_runtime.h>
#include <cuda_bf16.h>
#include <math.h>
#include <stdint.h>

typedef __nv_bfloat16 bf16;

// ---------------------------------------------------------------------------
// Static scratch (zero-init at module load; guard rows in g_XS never written).
// ---------------------------------------------------------------------------
__device__ bf16 g_XeS[75497472];    // Xe split  [32768][2304]  (hi|hi|lo)
__device__ bf16 g_XpS[31457280];    // Xp split  [32768][960]
__device__ bf16 g_W1S[1769472];     // W1 split  [768][2304]    (hi|lo|hi)
__device__ bf16 g_W2S[737280];      // W2 split  [768][960]
__device__ bf16 g_WcS[5308416];     // Wc split  [3 taps][768][2304] (hi|lo|hi)
__device__ bf16 g_XS [75792384];    // gated X split [64][514][2304], rows 0/513 = zero guards
__device__ float g_C2[25165824];    // raw C2 [32768][768]
__device__ float g_pool[147456];    // pooled [64][768][3]

#define STAGES 3
#define STAGE_BYTES 32768              // 16KB A tile + 16KB B tile
#define SMEM_BYTES (STAGES * STAGE_BYTES)

// ------------------------------- PTX helpers -------------------------------
__device__ __forceinline__ uint32_t s2u(const void* p){
    uint32_t a;
    asm("{ .reg .u64 t; cvta.to.shared.u64 t, %1; cvt.u32.u64 %0, t; }"
        : "=r"(a) : "l"(p));
    return a;
}
#define SWZ(x) ((x) ^ (((x) >> 3) & 0x70))

__device__ __forceinline__ void cpa16(uint32_t d, const void* s){
    asm volatile("cp.async.cg.shared.global [%0], [%1], 16;" :: "r"(d), "l"(s));
}
__device__ __forceinline__ void ldsm4(uint32_t& r0, uint32_t& r1,
                                      uint32_t& r2, uint32_t& r3, uint32_t a){
    asm volatile("ldmatrix.sync.aligned.m8n8.x4.shared.b16 {%0,%1,%2,%3}, [%4];"
        : "=r"(r0), "=r"(r1), "=r"(r2), "=r"(r3) : "r"(a));
}
__device__ __forceinline__ void mma16816(float* d, const uint32_t* a,
                                         uint32_t b0, uint32_t b1){
    asm volatile("mma.sync.aligned.m16n8k16.row.col.f32.bf16.bf16.f32 "
        "{%0,%1,%2,%3},{%4,%5,%6,%7},{%8,%9},{%0,%1,%2,%3};"
        : "+f"(d[0]), "+f"(d[1]), "+f"(d[2]), "+f"(d[3])
        : "r"(a[0]), "r"(a[1]), "r"(a[2]), "r"(a[3]), "r"(b0), "r"(b1));
}

// ------------------------- GEMM building blocks ----------------------------
// Stage tile: A 128 rows x 64 bf16 (128B SW128 rows), B same. 256 threads.
__device__ __forceinline__ void ld_stage(const char* Ap, const char* Bp,
                                         size_t kb, char* s){
    const int tid = threadIdx.x;
    uint32_t sa = s2u(s), sb = sa + 16384;
    #pragma unroll
    for (int i = 0; i < 4; i++){
        int idx = tid + i * 256;        // 1024 = 128 rows x 8 16B-units
        int row = idx >> 3;
        int q   = (idx & 7) << 4;
        cpa16(sa + SWZ(row * 128 + q), Ap + (size_t)row * kb + q);
        cpa16(sb + SWZ(row * 128 + q), Bp + (size_t)row * kb + q);
    }
}

__device__ __forceinline__ void compute_stage(char* s, int wm, int wn, int lane,
                                              float acc[4][4][4]){
    uint32_t sa = s2u(s), sb = sa + 16384;
    #pragma unroll
    for (int ks = 0; ks < 4; ks++){                   // 4 x k16 per BK=64
        uint32_t a[4][4];
        #pragma unroll
        for (int mi = 0; mi < 4; mi++){
            int row = wm * 64 + mi * 16 + (lane & 15);
            int kbb = ks * 32 + ((lane >> 4) << 4);
            ldsm4(a[mi][0], a[mi][1], a[mi][2], a[mi][3],
                  sa + SWZ(row * 128 + kbb));
        }
        uint32_t b[2][4];
        #pragma unroll
        for (int g = 0; g < 2; g++){
            int nrow = wn * 32 + g * 16 + (lane & 7) + ((lane >> 4) << 3);
            int kbb  = ks * 32 + (((lane >> 3) & 1) << 4);
            ldsm4(b[g][0], b[g][1], b[g][2], b[g][3],
                  sb + SWZ(nrow * 128 + kbb));
        }
        #pragma unroll
        for (int mi = 0; mi < 4; mi++)
            #pragma unroll
            for (int nj = 0; nj < 4; nj++)
                mma16816(acc[mi][nj], a[mi],
                         b[nj >> 1][(nj & 1) * 2], b[nj >> 1][(nj & 1) * 2 + 1]);
    }
}

// Pipelined GEMM over ntap A/B base pairs, npt BK=64 chunks each.
__device__ __forceinline__ void gemm_pipe(
    const bf16* A0, const bf16* A1, const bf16* A2,
    const bf16* B0, const bf16* B1, const bf16* B2,
    int npt, int ntap, size_t kE, char* sm, float acc[4][4][4])
{
    const size_t kb = kE * 2;
    const char* At[3] = {(const char*)A0, (const char*)A1, (const char*)A2};
    const char* Bt[3] = {(const char*)B0, (const char*)B1, (const char*)B2};
    const int nc   = npt * ntap;
    const int wid  = threadIdx.x >> 5, lane = threadIdx.x & 31;
    const int wm   = wid & 1, wn = wid >> 1;

    #pragma unroll
    for (int i = 0; i < 4; i++)
        #pragma unroll
        for (int j = 0; j < 4; j++)
            #pragma unroll
            for (int r = 0; r < 4; r++) acc[i][j][r] = 0.f;

    #pragma unroll
    for (int s = 0; s < STAGES - 1; s++){
        ld_stage(At[0] + (size_t)s * 128, Bt[0] + (size_t)s * 128, kb,
                 sm + s * STAGE_BYTES);
        asm volatile("cp.async.commit_group;");
    }
    int tap = 0, kc = STAGES - 1;           // next chunk to load (npt >= 15)

    for (int c = 0; c < nc; c++){
        asm volatile("cp.async.wait_group 1;");
        __syncthreads();
        int nx = c + STAGES - 1;
        if (nx < nc){
            ld_stage(At[tap] + (size_t)kc * 128, Bt[tap] + (size_t)kc * 128,
                     kb, sm + (nx % STAGES) * STAGE_BYTES);
            if (++kc == npt){ kc = 0; tap++; }
        }
        asm volatile("cp.async.commit_group;");   // empty group when tail
        compute_stage(sm + (c % STAGES) * STAGE_BYTES, wm, wn, lane, acc);
    }
    __syncthreads();
}

// ------------------------------- GEMM kernels ------------------------------
// C2 = XpS @ W2S^T (K=960), raw fp32 store.
__global__ __launch_bounds__(256) void gemm_p_kernel(){
    extern __shared__ char sm[];
    const int n0 = blockIdx.x * 128, m0 = blockIdx.y * 128;
    float acc[4][4][4];
    gemm_pipe(g_XpS + (size_t)m0 * 960, 0, 0,
              g_W2S + (size_t)n0 * 960, 0, 0, 15, 1, 960, sm, acc);
    const int wid = threadIdx.x >> 5, lane = threadIdx.x & 31;
    const int wm = wid & 1, wn = wid >> 1;
    #pragma unroll
    for (int mi = 0; mi < 4; mi++)
        #pragma unroll
        for (int nj = 0; nj < 4; nj++){
            int col = n0 + wn * 32 + nj * 8 + (lane & 3) * 2;
            #pragma unroll
            for (int h = 0; h < 2; h++){
                int m = m0 + wm * 64 + mi * 16 + (lane >> 2) + h * 8;
                float2 v = make_float2(acc[mi][nj][h * 2], acc[mi][nj][h * 2 + 1]);
                *(float2*)(g_C2 + (size_t)m * 768 + col) = v;
            }
        }
}

// C1 = XeS @ W1S^T (K=2304); epilogue: gate + mix + bf16 split -> g_XS.
__global__ __launch_bounds__(256) void gemm_e_kernel(
    const float* __restrict__ Xe, const float* __restrict__ b1,
    const float* __restrict__ b2)
{
    extern __shared__ char sm[];
    const int n0 = blockIdx.x * 128, m0 = blockIdx.y * 128;
    float acc[4][4][4];
    gemm_pipe(g_XeS + (size_t)m0 * 2304, 0, 0,
              g_W1S + (size_t)n0 * 2304, 0, 0, 36, 1, 2304, sm, acc);
    const int wid = threadIdx.x >> 5, lane = threadIdx.x & 31;
    const int wm = wid & 1, wn = wid >> 1;
    const int bb = m0 >> 9;
    #pragma unroll
    for (int mi = 0; mi < 4; mi++)
        #pragma unroll
        for (int nj = 0; nj < 4; nj++){
            int col = n0 + wn * 32 + nj * 8 + (lane & 3) * 2;
            float b1a = b1[col], b1b = b1[col + 1];
            float b2a = b2[col], b2b = b2[col + 1];
            #pragma unroll
            for (int h = 0; h < 2; h++){
                int m = m0 + wm * 64 + mi * 16 + (lane >> 2) + h * 8;
                float2 c2 = *(const float2*)(g_C2 + (size_t)m * 768 + col);
                float2 xe = *(const float2*)(Xe   + (size_t)m * 768 + col);
                float g0 = 1.f / (1.f + __expf(-(acc[mi][nj][h * 2]     + b1a)));
                float g1 = 1.f / (1.f + __expf(-(acc[mi][nj][h * 2 + 1] + b1b)));
                float X0 = g0 * xe.x + (1.f - g0) * tanhf(c2.x + b2a);
                float X1 = g1 * xe.y + (1.f - g1) * tanhf(c2.y + b2b);
                bf16 h0 = __float2bfloat16(X0);
                bf16 l0 = __float2bfloat16(X0 - __bfloat162float(h0));
                bf16 h1 = __float2bfloat16(X1);
                bf16 l1 = __float2bfloat16(X1 - __bfloat162float(h1));
                __nv_bfloat162 H; H.x = h0; H.y = h1;
                __nv_bfloat162 L; L.x = l0; L.y = l1;
                int rowp = bb * 514 + 1 + (m & 511);
                bf16* d0 = g_XS + (size_t)rowp * 2304 + col;
                *(__nv_bfloat162*)(d0)        = H;   // seg0: hi
                *(__nv_bfloat162*)(d0 + 768)  = H;   // seg1: hi
                *(__nv_bfloat162*)(d0 + 1536) = L;   // seg2: lo
            }
        }
}

// Conv: 3 accumulating passes (A row-shifted by tap) + fused piecewise max-pool.
__global__ __launch_bounds__(256) void gemm_c_kernel(
    const int* __restrict__ Xmask, const float* __restrict__ bc)
{
    extern __shared__ char sm[];
    const int n0 = blockIdx.x * 128, m0 = blockIdx.y * 128;
    const int bb = m0 >> 9, r0 = m0 & 511;
    const bf16* Ab = g_XS  + (size_t)(bb * 514 + r0) * 2304;  // tap t -> +t rows
    const bf16* Bb = g_WcS + (size_t)n0 * 2304;
    float acc[4][4][4];
    gemm_pipe(Ab, Ab + 2304, Ab + 2 * 2304,
              Bb, Bb + 1769472, Bb + 2 * 1769472,
              36, 3, 2304, sm, acc);

    const int wid = threadIdx.x >> 5, lane = threadIdx.x & 31;
    const int wm = wid & 1, wn = wid >> 1;
    int* red = (int*)sm;                  // [3][128] float-bit maxima
    for (int e = threadIdx.x; e < 384; e += 256) red[e] = 0;
    __syncthreads();

    #pragma unroll
    for (int mi = 0; mi < 4; mi++)
        #pragma unroll
        for (int nj = 0; nj < 4; nj++){
            int col = n0 + wn * 32 + nj * 8 + (lane & 3) * 2;
            float bca = bc[col], bcb = bc[col + 1];
            #pragma unroll
            for (int h = 0; h < 2; h++){
                int m  = m0 + wm * 64 + mi * 16 + (lane >> 2) + h * 8;
                int mk = Xmask[m];
                if (mk){
                    int base = (mk - 1) * 128 + (col - n0);
                    atomicMax(&red[base],     __float_as_int(acc[mi][nj][h * 2]     + bca));
                    atomicMax(&red[base + 1], __float_as_int(acc[mi][nj][h * 2 + 1] + bcb));
                }
            }
        }
    __syncthreads();
    for (int e = threadIdx.x; e < 384; e += 256){
        int k = e >> 7, c = e & 127;
        atomicMax((int*)&g_pool[((size_t)bb * 768 + n0 + c) * 3 + k], red[e]);
    }
}

// ------------------------------ small kernels ------------------------------
// fp32 -> bf16 hi/lo split, K-tripled: A-side segs (hi,hi,lo), B-side (hi,lo,hi)
__global__ __launch_bounds__(256) void cvt_split_kernel(
    const float* __restrict__ in, int which, int C, int npair, int sideB)
{
    int i = blockIdx.x * 256 + threadIdx.x;
    if (i >= npair) return;
    bf16* out = which == 0 ? g_XeS : which == 1 ? g_XpS
              : which == 2 ? g_W1S : g_W2S;
    float2 v = *(const float2*)(in + (size_t)i * 2);
    int e = i * 2, r = e / C, c = e - r * C;
    bf16 hx = __float2bfloat16(v.x);
    bf16 lx = __float2bfloat16(v.x - __bfloat162float(hx));
    bf16 hy = __float2bfloat16(v.y);
    bf16 ly = __float2bfloat16(v.y - __bfloat162float(hy));
    __nv_bfloat162 H; H.x = hx; H.y = hy;
    __nv_bfloat162 L; L.x = lx; L.y = ly;
    bf16* o = out + (size_t)r * 3 * C + c;
    *(__nv_bfloat162*)(o)         = H;
    *(__nv_bfloat162*)(o + C)     = sideB ? L : H;
    *(__nv_bfloat162*)(o + 2 * C) = sideB ? H : L;
}

// Wc [o][i][t] -> g_WcS[t][o][ seg*768 + i ], segs (hi, lo, hi)
__global__ __launch_bounds__(256) void cvt_wc_kernel(const float* __restrict__ Wc){
    int idx = blockIdx.x * 256 + threadIdx.x;
    if (idx >= 589824) return;
    int o = idx / 768, i = idx - o * 768;
    const float* src = Wc + (size_t)idx * 3;
    #pragma unroll
    for (int t = 0; t < 3; t++){
        float v = src[t];
        bf16 h = __float2bfloat16(v);
        bf16 l = __float2bfloat16(v - __bfloat162float(h));
        bf16* d = g_WcS + (size_t)t * 1769472 + (size_t)o * 2304 + i;
        d[0]    = h;
        d[768]  = l;
        d[1536] = h;
    }
}

__global__ void init_pool_kernel(){
    int i = blockIdx.x * 256 + threadIdx.x;
    if (i < 147456) g_pool[i] = 0.f;
}
__global__ void final_kernel(float* __restrict__ out){
    int i = blockIdx.x * 256 + threadIdx.x;
    if (i < 147456) out[i] = tanhf(g_pool[i]);
}

// ---------------------------------------------------------------------------
extern "C" void kernel_launch(void* const* d_in, const int* in_sizes, int n_in,
                              void* d_out, int out_size)
{
    const float* Xp = (const float*)d_in[0];
    const float* Xe = (const float*)d_in[1];
    const int*   Xm = (const int*)  d_in[2];
    const float* W1 = (const float*)d_in[3];
    const float* b1 = (const float*)d_in[4];
    const float* W2 = (const float*)d_in[5];
    const float* b2 = (const float*)d_in[6];
    const float* Wc = (const float*)d_in[7];
    const float* bc = (const float*)d_in[8];
    float* out = (float*)d_out;

    cudaFuncSetAttribute(gemm_p_kernel, cudaFuncAttributeMaxDynamicSharedMemorySize, SMEM_BYTES);
    cudaFuncSetAttribute(gemm_e_kernel, cudaFuncAttributeMaxDynamicSharedMemorySize, SMEM_BYTES);
    cudaFuncSetAttribute(gemm_c_kernel, cudaFuncAttributeMaxDynamicSharedMemorySize, SMEM_BYTES);

    init_pool_kernel<<<576, 256>>>();
    cvt_split_kernel<<<(12582912 + 255) / 256, 256>>>(Xe, 0, 768, 12582912, 0);
    cvt_split_kernel<<<( 5242880 + 255) / 256, 256>>>(Xp, 1, 320,  5242880, 0);
    cvt_split_kernel<<<(  294912 + 255) / 256, 256>>>(W1, 2, 768,   294912, 1);
    cvt_split_kernel<<<(  122880 + 255) / 256, 256>>>(W2, 3, 320,   122880, 1);
    cvt_wc_kernel<<<2304, 256>>>(Wc);

    dim3 gg(6, 256);   // 6 N-tiles x 256 M-tiles
    gemm_p_kernel<<<gg, 256, SMEM_BYTES>>>();
    gemm_e_kernel<<<gg, 256, SMEM_BYTES>>>(Xe, b1, b2);
    gemm_c_kernel<<<gg, 256, SMEM_BYTES>>>(Xm, bc);

    final_kernel<<<576, 256>>>(out);
}

// round 10
// speedup vs baseline: 10.5728x; 1.6628x over previous
#include <cuda_runtime.h>
#include <cuda_fp16.h>
#include <math.h>
#include <stdint.h>

typedef __half f16;

// ---------------------------------------------------------------------------
// Static scratch (zero-init at load; guard rows in g_XS never written).
// ---------------------------------------------------------------------------
__device__ f16 g_XeH[25165824];     // Xe fp16 [32768][768]
__device__ f16 g_XpH[10485760];     // Xp fp16 [32768][320]
__device__ f16 g_W1H[589824];       // W1 fp16 [768][768]
__device__ f16 g_W2H[245760];       // W2 fp16 [768][320]
__device__ f16 g_WcH[1769472];      // Wc fp16 [3 taps][768][768]
__device__ f16 g_XS [25264128];     // gated X fp16 [64][514][768], rows 0/513 zero guards
__device__ float g_C2[25165824];    // raw C2 [32768][768]
__device__ float g_pool[147456];    // pooled [64][768][3]

#define STAGES 3
#define STAGE_BYTES 32768              // 16KB A tile + 16KB B tile
#define SMEM_BYTES (STAGES * STAGE_BYTES)

// ------------------------------- PTX helpers -------------------------------
__device__ __forceinline__ uint32_t s2u(const void* p){
    uint32_t a;
    asm("{ .reg .u64 t; cvta.to.shared.u64 t, %1; cvt.u32.u64 %0, t; }"
        : "=r"(a) : "l"(p));
    return a;
}
#define SWZ(x) ((x) ^ (((x) >> 3) & 0x70))

__device__ __forceinline__ void cpa16(uint32_t d, const void* s){
    asm volatile("cp.async.cg.shared.global [%0], [%1], 16;" :: "r"(d), "l"(s));
}
__device__ __forceinline__ void ldsm4(uint32_t& r0, uint32_t& r1,
                                      uint32_t& r2, uint32_t& r3, uint32_t a){
    asm volatile("ldmatrix.sync.aligned.m8n8.x4.shared.b16 {%0,%1,%2,%3}, [%4];"
        : "=r"(r0), "=r"(r1), "=r"(r2), "=r"(r3) : "r"(a));
}
__device__ __forceinline__ void mma16816(float* d, const uint32_t* a,
                                         uint32_t b0, uint32_t b1){
    asm volatile("mma.sync.aligned.m16n8k16.row.col.f32.f16.f16.f32 "
        "{%0,%1,%2,%3},{%4,%5,%6,%7},{%8,%9},{%0,%1,%2,%3};"
        : "+f"(d[0]), "+f"(d[1]), "+f"(d[2]), "+f"(d[3])
        : "r"(a[0]), "r"(a[1]), "r"(a[2]), "r"(a[3]), "r"(b0), "r"(b1));
}

// ------------------------- GEMM building blocks ----------------------------
// Stage tile: A 128 rows x 64 f16 (128B SW128 rows), B same. 256 threads.
__device__ __forceinline__ void ld_stage(const char* Ap, const char* Bp,
                                         size_t kb, char* s){
    const int tid = threadIdx.x;
    uint32_t sa = s2u(s), sb = sa + 16384;
    #pragma unroll
    for (int i = 0; i < 4; i++){
        int idx = tid + i * 256;        // 1024 = 128 rows x 8 16B-units
        int row = idx >> 3;
        int q   = (idx & 7) << 4;
        cpa16(sa + SWZ(row * 128 + q), Ap + (size_t)row * kb + q);
        cpa16(sb + SWZ(row * 128 + q), Bp + (size_t)row * kb + q);
    }
}

__device__ __forceinline__ void compute_stage(char* s, int wm, int wn, int lane,
                                              float acc[4][4][4]){
    uint32_t sa = s2u(s), sb = sa + 16384;
    #pragma unroll
    for (int ks = 0; ks < 4; ks++){                   // 4 x k16 per BK=64
        uint32_t a[4][4];
        #pragma unroll
        for (int mi = 0; mi < 4; mi++){
            int row = wm * 64 + mi * 16 + (lane & 15);
            int kbb = ks * 32 + ((lane >> 4) << 4);
            ldsm4(a[mi][0], a[mi][1], a[mi][2], a[mi][3],
                  sa + SWZ(row * 128 + kbb));
        }
        uint32_t b[2][4];
        #pragma unroll
        for (int g = 0; g < 2; g++){
            int nrow = wn * 32 + g * 16 + (lane & 7) + ((lane >> 4) << 3);
            int kbb  = ks * 32 + (((lane >> 3) & 1) << 4);
            ldsm4(b[g][0], b[g][1], b[g][2], b[g][3],
                  sb + SWZ(nrow * 128 + kbb));
        }
        #pragma unroll
        for (int mi = 0; mi < 4; mi++)
            #pragma unroll
            for (int nj = 0; nj < 4; nj++)
                mma16816(acc[mi][nj], a[mi],
                         b[nj >> 1][(nj & 1) * 2], b[nj >> 1][(nj & 1) * 2 + 1]);
    }
}

// Pipelined GEMM over ntap A/B base pairs, npt BK=64 chunks each.
__device__ __forceinline__ void gemm_pipe(
    const f16* A0, const f16* A1, const f16* A2,
    const f16* B0, const f16* B1, const f16* B2,
    int npt, int ntap, size_t kE, char* sm, float acc[4][4][4])
{
    const size_t kb = kE * 2;
    const char* At[3] = {(const char*)A0, (const char*)A1, (const char*)A2};
    const char* Bt[3] = {(const char*)B0, (const char*)B1, (const char*)B2};
    const int nc   = npt * ntap;
    const int wid  = threadIdx.x >> 5, lane = threadIdx.x & 31;
    const int wm   = wid & 1, wn = wid >> 1;

    #pragma unroll
    for (int i = 0; i < 4; i++)
        #pragma unroll
        for (int j = 0; j < 4; j++)
            #pragma unroll
            for (int r = 0; r < 4; r++) acc[i][j][r] = 0.f;

    #pragma unroll
    for (int s = 0; s < STAGES - 1; s++){
        ld_stage(At[0] + (size_t)s * 128, Bt[0] + (size_t)s * 128, kb,
                 sm + s * STAGE_BYTES);
        asm volatile("cp.async.commit_group;");
    }
    int tap = 0, kc = STAGES - 1;           // next chunk to load (npt >= 5)

    for (int c = 0; c < nc; c++){
        asm volatile("cp.async.wait_group 1;");
        __syncthreads();
        int nx = c + STAGES - 1;
        if (nx < nc){
            ld_stage(At[tap] + (size_t)kc * 128, Bt[tap] + (size_t)kc * 128,
                     kb, sm + (nx % STAGES) * STAGE_BYTES);
            if (++kc == npt){ kc = 0; tap++; }
        }
        asm volatile("cp.async.commit_group;");   // empty group when tail
        compute_stage(sm + (c % STAGES) * STAGE_BYTES, wm, wn, lane, acc);
    }
    __syncthreads();
}

// ------------------------------- GEMM kernels ------------------------------
// C2 = XpH @ W2H^T (K=320), raw fp32 store.
__global__ __launch_bounds__(256) void gemm_p_kernel(){
    extern __shared__ char sm[];
    const int n0 = blockIdx.x * 128, m0 = blockIdx.y * 128;
    float acc[4][4][4];
    gemm_pipe(g_XpH + (size_t)m0 * 320, 0, 0,
              g_W2H + (size_t)n0 * 320, 0, 0, 5, 1, 320, sm, acc);
    const int wid = threadIdx.x >> 5, lane = threadIdx.x & 31;
    const int wm = wid & 1, wn = wid >> 1;
    #pragma unroll
    for (int mi = 0; mi < 4; mi++)
        #pragma unroll
        for (int nj = 0; nj < 4; nj++){
            int col = n0 + wn * 32 + nj * 8 + (lane & 3) * 2;
            #pragma unroll
            for (int h = 0; h < 2; h++){
                int m = m0 + wm * 64 + mi * 16 + (lane >> 2) + h * 8;
                float2 v = make_float2(acc[mi][nj][h * 2], acc[mi][nj][h * 2 + 1]);
                *(float2*)(g_C2 + (size_t)m * 768 + col) = v;
            }
        }
}

// C1 = XeH @ W1H^T (K=768); epilogue: gate + mix -> fp16 X in g_XS.
__global__ __launch_bounds__(256) void gemm_e_kernel(
    const float* __restrict__ Xe, const float* __restrict__ b1,
    const float* __restrict__ b2)
{
    extern __shared__ char sm[];
    const int n0 = blockIdx.x * 128, m0 = blockIdx.y * 128;
    float acc[4][4][4];
    gemm_pipe(g_XeH + (size_t)m0 * 768, 0, 0,
              g_W1H + (size_t)n0 * 768, 0, 0, 12, 1, 768, sm, acc);
    const int wid = threadIdx.x >> 5, lane = threadIdx.x & 31;
    const int wm = wid & 1, wn = wid >> 1;
    const int bb = m0 >> 9;
    #pragma unroll
    for (int mi = 0; mi < 4; mi++)
        #pragma unroll
        for (int nj = 0; nj < 4; nj++){
            int col = n0 + wn * 32 + nj * 8 + (lane & 3) * 2;
            float b1a = b1[col], b1b = b1[col + 1];
            float b2a = b2[col], b2b = b2[col + 1];
            #pragma unroll
            for (int h = 0; h < 2; h++){
                int m = m0 + wm * 64 + mi * 16 + (lane >> 2) + h * 8;
                float2 c2 = *(const float2*)(g_C2 + (size_t)m * 768 + col);
                float2 xe = *(const float2*)(Xe   + (size_t)m * 768 + col);
                float g0 = 1.f / (1.f + __expf(-(acc[mi][nj][h * 2]     + b1a)));
                float g1 = 1.f / (1.f + __expf(-(acc[mi][nj][h * 2 + 1] + b1b)));
                float X0 = g0 * xe.x + (1.f - g0) * tanhf(c2.x + b2a);
                float X1 = g1 * xe.y + (1.f - g1) * tanhf(c2.y + b2b);
                __half2 H = __floats2half2_rn(X0, X1);
                int rowp = bb * 514 + 1 + (m & 511);
                *(__half2*)(g_XS + (size_t)rowp * 768 + col) = H;
            }
        }
}

// Conv: 3 accumulating passes (A row-shifted by tap) + fused piecewise max-pool.
__global__ __launch_bounds__(256) void gemm_c_kernel(
    const int* __restrict__ Xmask, const float* __restrict__ bc)
{
    extern __shared__ char sm[];
    const int n0 = blockIdx.x * 128, m0 = blockIdx.y * 128;
    const int bb = m0 >> 9, r0 = m0 & 511;
    const f16* Ab = g_XS  + (size_t)(bb * 514 + r0) * 768;   // tap t -> +t rows
    const f16* Bb = g_WcH + (size_t)n0 * 768;
    float acc[4][4][4];
    gemm_pipe(Ab, Ab + 768, Ab + 2 * 768,
              Bb, Bb + 589824, Bb + 2 * 589824,
              12, 3, 768, sm, acc);

    const int wid = threadIdx.x >> 5, lane = threadIdx.x & 31;
    const int wm = wid & 1, wn = wid >> 1;
    int* red = (int*)sm;                  // [3][128] float-bit maxima
    for (int e = threadIdx.x; e < 384; e += 256) red[e] = 0;
    __syncthreads();

    #pragma unroll
    for (int mi = 0; mi < 4; mi++)
        #pragma unroll
        for (int nj = 0; nj < 4; nj++){
            int col = n0 + wn * 32 + nj * 8 + (lane & 3) * 2;
            float bca = bc[col], bcb = bc[col + 1];
            #pragma unroll
            for (int h = 0; h < 2; h++){
                int m  = m0 + wm * 64 + mi * 16 + (lane >> 2) + h * 8;
                int mk = Xmask[m];
                if (mk){
                    int base = (mk - 1) * 128 + (col - n0);
                    atomicMax(&red[base],     __float_as_int(acc[mi][nj][h * 2]     + bca));
                    atomicMax(&red[base + 1], __float_as_int(acc[mi][nj][h * 2 + 1] + bcb));
                }
            }
        }
    __syncthreads();
    for (int e = threadIdx.x; e < 384; e += 256){
        int k = e >> 7, c = e & 127;
        atomicMax((int*)&g_pool[((size_t)bb * 768 + n0 + c) * 3 + k], red[e]);
    }
}

// ------------------------------ small kernels ------------------------------
// fp32 -> fp16 copy, 4 elems/thread.
__global__ __launch_bounds__(256) void cvt_kernel(
    const float* __restrict__ in, int which, int n4)
{
    int i = blockIdx.x * 256 + threadIdx.x;
    if (i >= n4) return;
    f16* out = which == 0 ? g_XeH : which == 1 ? g_XpH
             : which == 2 ? g_W1H : g_W2H;
    float4 v = *(const float4*)(in + (size_t)i * 4);
    __half2 a = __floats2half2_rn(v.x, v.y);
    __half2 b = __floats2half2_rn(v.z, v.w);
    uint2 u;
    u.x = *(uint32_t*)&a;
    u.y = *(uint32_t*)&b;
    *(uint2*)(out + (size_t)i * 4) = u;
}

// Wc [o][i][t] -> g_WcH[t][o][i]
__global__ __launch_bounds__(256) void cvt_wc_kernel(const float* __restrict__ Wc){
    int idx = blockIdx.x * 256 + threadIdx.x;
    if (idx >= 589824) return;
    const float* src = Wc + (size_t)idx * 3;
    #pragma unroll
    for (int t = 0; t < 3; t++)
        g_WcH[(size_t)t * 589824 + idx] = __float2half_rn(src[t]);
}

__global__ void init_pool_kernel(){
    int i = blockIdx.x * 256 + threadIdx.x;
    if (i < 147456) g_pool[i] = 0.f;
}
__global__ void final_kernel(float* __restrict__ out){
    int i = blockIdx.x * 256 + threadIdx.x;
    if (i < 147456) out[i] = tanhf(g_pool[i]);
}

// ---------------------------------------------------------------------------
extern "C" void kernel_launch(void* const* d_in, const int* in_sizes, int n_in,
                              void* d_out, int out_size)
{
    const float* Xp = (const float*)d_in[0];
    const float* Xe = (const float*)d_in[1];
    const int*   Xm = (const int*)  d_in[2];
    const float* W1 = (const float*)d_in[3];
    const float* b1 = (const float*)d_in[4];
    const float* W2 = (const float*)d_in[5];
    const float* b2 = (const float*)d_in[6];
    const float* Wc = (const float*)d_in[7];
    const float* bc = (const float*)d_in[8];
    float* out = (float*)d_out;

    cudaFuncSetAttribute(gemm_p_kernel, cudaFuncAttributeMaxDynamicSharedMemorySize, SMEM_BYTES);
    cudaFuncSetAttribute(gemm_e_kernel, cudaFuncAttributeMaxDynamicSharedMemorySize, SMEM_BYTES);
    cudaFuncSetAttribute(gemm_c_kernel, cudaFuncAttributeMaxDynamicSharedMemorySize, SMEM_BYTES);

    init_pool_kernel<<<576, 256>>>();
    cvt_kernel<<<(6291456 + 255) / 256, 256>>>(Xe, 0, 6291456);
    cvt_kernel<<<(2621440 + 255) / 256, 256>>>(Xp, 1, 2621440);
    cvt_kernel<<<( 147456 + 255) / 256, 256>>>(W1, 2,  147456);
    cvt_kernel<<<(  61440 + 255) / 256, 256>>>(W2, 3,   61440);
    cvt_wc_kernel<<<2304, 256>>>(Wc);

    dim3 gg(6, 256);   // 6 N-tiles x 256 M-tiles
    gemm_p_kernel<<<gg, 256, SMEM_BYTES>>>();
    gemm_e_kernel<<<gg, 256, SMEM_BYTES>>>(Xe, b1, b2);
    gemm_c_kernel<<<gg, 256, SMEM_BYTES>>>(Xm, bc);

    final_kernel<<<576, 256>>>(out);
}

// round 12
// speedup vs baseline: 15.4449x; 1.4608x over previous
#include <cuda_runtime.h>
#include <cuda_fp16.h>
#include <math.h>
#include <stdint.h>

typedef __half f16;

// ---------------------------------------------------------------------------
// Static scratch (zero-init at load; guard rows in g_XS never written).
// ---------------------------------------------------------------------------
__device__ f16 g_XeH[25165824];     // Xe fp16 [32768][768]
__device__ f16 g_XpH[10485760];     // Xp fp16 [32768][320]
__device__ f16 g_W1H[589824];       // W1 fp16 [768][768]
__device__ f16 g_W2H[245760];       // W2 fp16 [768][320]
__device__ f16 g_WcH[1769472];      // Wc fp16 [3 taps][768][768]
__device__ f16 g_XS [25264128];     // gated X fp16 [64][514][768], rows 0/513 zero guards
__device__ f16 g_PV [25165824];     // pv = tanh(C2+b2) fp16 [32768][768]
__device__ float g_pool[147456];    // pooled [64][768][3]

#define STAGES 3
#define STAGE_BYTES 32768              // 16KB A tile + 16KB B tile
#define SMEM_BYTES (STAGES * STAGE_BYTES)

// ------------------------------- PTX helpers -------------------------------
__device__ __forceinline__ uint32_t s2u(const void* p){
    uint32_t a;
    asm("{ .reg .u64 t; cvta.to.shared.u64 t, %1; cvt.u32.u64 %0, t; }"
        : "=r"(a) : "l"(p));
    return a;
}
#define SWZ(x) ((x) ^ (((x) >> 3) & 0x70))

__device__ __forceinline__ void cpa16(uint32_t d, const void* s){
    asm volatile("cp.async.cg.shared.global [%0], [%1], 16;" :: "r"(d), "l"(s));
}
__device__ __forceinline__ void ldsm4(uint32_t& r0, uint32_t& r1,
                                      uint32_t& r2, uint32_t& r3, uint32_t a){
    asm volatile("ldmatrix.sync.aligned.m8n8.x4.shared.b16 {%0,%1,%2,%3}, [%4];"
        : "=r"(r0), "=r"(r1), "=r"(r2), "=r"(r3) : "r"(a));
}
__device__ __forceinline__ void mma16816(float* d, const uint32_t* a,
                                         uint32_t b0, uint32_t b1){
    asm volatile("mma.sync.aligned.m16n8k16.row.col.f32.f16.f16.f32 "
        "{%0,%1,%2,%3},{%4,%5,%6,%7},{%8,%9},{%0,%1,%2,%3};"
        : "+f"(d[0]), "+f"(d[1]), "+f"(d[2]), "+f"(d[3])
        : "r"(a[0]), "r"(a[1]), "r"(a[2]), "r"(a[3]), "r"(b0), "r"(b1));
}

// ------------------------- GEMM building blocks ----------------------------
// Stage tile: A 128 rows x 64 f16 (128B SW128 rows), B same. 256 threads.
__device__ __forceinline__ void ld_stage(const char* Ap, const char* Bp,
                                         size_t kb, char* s){
    const int tid = threadIdx.x;
    uint32_t sa = s2u(s), sb = sa + 16384;
    #pragma unroll
    for (int i = 0; i < 4; i++){
        int idx = tid + i * 256;        // 1024 = 128 rows x 8 16B-units
        int row = idx >> 3;
        int q   = (idx & 7) << 4;
        cpa16(sa + SWZ(row * 128 + q), Ap + (size_t)row * kb + q);
        cpa16(sb + SWZ(row * 128 + q), Bp + (size_t)row * kb + q);
    }
}

__device__ __forceinline__ void compute_stage(char* s, int wm, int wn, int lane,
                                              float acc[4][4][4]){
    uint32_t sa = s2u(s), sb = sa + 16384;
    #pragma unroll
    for (int ks = 0; ks < 4; ks++){                   // 4 x k16 per BK=64
        uint32_t a[4][4];
        #pragma unroll
        for (int mi = 0; mi < 4; mi++){
            int row = wm * 64 + mi * 16 + (lane & 15);
            int kbb = ks * 32 + ((lane >> 4) << 4);
            ldsm4(a[mi][0], a[mi][1], a[mi][2], a[mi][3],
                  sa + SWZ(row * 128 + kbb));
        }
        uint32_t b[2][4];
        #pragma unroll
        for (int g = 0; g < 2; g++){
            int nrow = wn * 32 + g * 16 + (lane & 7) + ((lane >> 4) << 3);
            int kbb  = ks * 32 + (((lane >> 3) & 1) << 4);
            ldsm4(b[g][0], b[g][1], b[g][2], b[g][3],
                  sb + SWZ(nrow * 128 + kbb));
        }
        #pragma unroll
        for (int mi = 0; mi < 4; mi++)
            #pragma unroll
            for (int nj = 0; nj < 4; nj++)
                mma16816(acc[mi][nj], a[mi],
                         b[nj >> 1][(nj & 1) * 2], b[nj >> 1][(nj & 1) * 2 + 1]);
    }
}

// Pipelined GEMM over ntap A/B base pairs, npt BK=64 chunks each.
__device__ __forceinline__ void gemm_pipe(
    const f16* A0, const f16* A1, const f16* A2,
    const f16* B0, const f16* B1, const f16* B2,
    int npt, int ntap, size_t kE, char* sm, float acc[4][4][4])
{
    const size_t kb = kE * 2;
    const char* At[3] = {(const char*)A0, (const char*)A1, (const char*)A2};
    const char* Bt[3] = {(const char*)B0, (const char*)B1, (const char*)B2};
    const int nc   = npt * ntap;
    const int wid  = threadIdx.x >> 5, lane = threadIdx.x & 31;
    const int wm   = wid & 1, wn = wid >> 1;

    #pragma unroll
    for (int i = 0; i < 4; i++)
        #pragma unroll
        for (int j = 0; j < 4; j++)
            #pragma unroll
            for (int r = 0; r < 4; r++) acc[i][j][r] = 0.f;

    #pragma unroll
    for (int s = 0; s < STAGES - 1; s++){
        ld_stage(At[0] + (size_t)s * 128, Bt[0] + (size_t)s * 128, kb,
                 sm + s * STAGE_BYTES);
        asm volatile("cp.async.commit_group;");
    }
    int tap = 0, kc = STAGES - 1;           // next chunk to load (npt >= 5)

    for (int c = 0; c < nc; c++){
        asm volatile("cp.async.wait_group 1;");
        __syncthreads();
        int nx = c + STAGES - 1;
        if (nx < nc){
            ld_stage(At[tap] + (size_t)kc * 128, Bt[tap] + (size_t)kc * 128,
                     kb, sm + (nx % STAGES) * STAGE_BYTES);
            if (++kc == npt){ kc = 0; tap++; }
        }
        asm volatile("cp.async.commit_group;");   // empty group when tail
        compute_stage(sm + (c % STAGES) * STAGE_BYTES, wm, wn, lane, acc);
    }
    __syncthreads();
}

// ------------------------------- GEMM kernels ------------------------------
// pv = tanh(XpH @ W2H^T + b2) (K=320), fp16 store.
__global__ __launch_bounds__(256) void gemm_p_kernel(const float* __restrict__ b2){
    extern __shared__ char sm[];
    const int n0 = blockIdx.x * 128, m0 = blockIdx.y * 128;
    float acc[4][4][4];
    gemm_pipe(g_XpH + (size_t)m0 * 320, 0, 0,
              g_W2H + (size_t)n0 * 320, 0, 0, 5, 1, 320, sm, acc);
    const int wid = threadIdx.x >> 5, lane = threadIdx.x & 31;
    const int wm = wid & 1, wn = wid >> 1;
    #pragma unroll
    for (int mi = 0; mi < 4; mi++)
        #pragma unroll
        for (int nj = 0; nj < 4; nj++){
            int col = n0 + wn * 32 + nj * 8 + (lane & 3) * 2;
            float b2a = b2[col], b2b = b2[col + 1];
            #pragma unroll
            for (int h = 0; h < 2; h++){
                int m = m0 + wm * 64 + mi * 16 + (lane >> 2) + h * 8;
                float p0 = tanhf(acc[mi][nj][h * 2]     + b2a);
                float p1 = tanhf(acc[mi][nj][h * 2 + 1] + b2b);
                *(__half2*)(g_PV + (size_t)m * 768 + col) = __floats2half2_rn(p0, p1);
            }
        }
}

// C1 = XeH @ W1H^T (K=768); epilogue: gate + mix -> fp16 X in g_XS.
__global__ __launch_bounds__(256) void gemm_e_kernel(
    const float* __restrict__ Xe, const float* __restrict__ b1)
{
    extern __shared__ char sm[];
    const int n0 = blockIdx.x * 128, m0 = blockIdx.y * 128;
    float acc[4][4][4];
    gemm_pipe(g_XeH + (size_t)m0 * 768, 0, 0,
              g_W1H + (size_t)n0 * 768, 0, 0, 12, 1, 768, sm, acc);
    const int wid = threadIdx.x >> 5, lane = threadIdx.x & 31;
    const int wm = wid & 1, wn = wid >> 1;
    const int bb = m0 >> 9;
    #pragma unroll
    for (int mi = 0; mi < 4; mi++)
        #pragma unroll
        for (int nj = 0; nj < 4; nj++){
            int col = n0 + wn * 32 + nj * 8 + (lane & 3) * 2;
            float b1a = b1[col], b1b = b1[col + 1];
            #pragma unroll
            for (int h = 0; h < 2; h++){
                int m = m0 + wm * 64 + mi * 16 + (lane >> 2) + h * 8;
                float2 xe = *(const float2*)(Xe + (size_t)m * 768 + col);
                __half2 pv = *(const __half2*)(g_PV + (size_t)m * 768 + col);
                float2 pvf = __half22float2(pv);
                float g0 = 1.f / (1.f + __expf(-(acc[mi][nj][h * 2]     + b1a)));
                float g1 = 1.f / (1.f + __expf(-(acc[mi][nj][h * 2 + 1] + b1b)));
                float X0 = g0 * xe.x + (1.f - g0) * pvf.x;
                float X1 = g1 * xe.y + (1.f - g1) * pvf.y;
                __half2 H = __floats2half2_rn(X0, X1);
                int rowp = bb * 514 + 1 + (m & 511);
                *(__half2*)(g_XS + (size_t)rowp * 768 + col) = H;
            }
        }
}

// Conv: 3 accumulating passes (A row-shifted by tap) + fused piecewise max-pool.
__global__ __launch_bounds__(256) void gemm_c_kernel(
    const int* __restrict__ Xmask, const float* __restrict__ bc)
{
    extern __shared__ char sm[];
    const int n0 = blockIdx.x * 128, m0 = blockIdx.y * 128;
    const int bb = m0 >> 9, r0 = m0 & 511;
    const f16* Ab = g_XS  + (size_t)(bb * 514 + r0) * 768;   // tap t -> +t rows
    const f16* Bb = g_WcH + (size_t)n0 * 768;
    float acc[4][4][4];
    gemm_pipe(Ab, Ab + 768, Ab + 2 * 768,
              Bb, Bb + 589824, Bb + 2 * 589824,
              12, 3, 768, sm, acc);

    const int wid = threadIdx.x >> 5, lane = threadIdx.x & 31;
    const int wm = wid & 1, wn = wid >> 1;
    int* red = (int*)sm;                  // [3][128] float-bit maxima
    for (int e = threadIdx.x; e < 384; e += 256) red[e] = 0;
    __syncthreads();

    #pragma unroll
    for (int mi = 0; mi < 4; mi++)
        #pragma unroll
        for (int nj = 0; nj < 4; nj++){
            int col = n0 + wn * 32 + nj * 8 + (lane & 3) * 2;
            float bca = bc[col], bcb = bc[col + 1];
            #pragma unroll
            for (int h = 0; h < 2; h++){
                int m  = m0 + wm * 64 + mi * 16 + (lane >> 2) + h * 8;
                int mk = Xmask[m];
                if (mk){
                    int base = (mk - 1) * 128 + (col - n0);
                    atomicMax(&red[base],     __float_as_int(acc[mi][nj][h * 2]     + bca));
                    atomicMax(&red[base + 1], __float_as_int(acc[mi][nj][h * 2 + 1] + bcb));
                }
            }
        }
    __syncthreads();
    for (int e = threadIdx.x; e < 384; e += 256){
        int k = e >> 7, c = e & 127;
        atomicMax((int*)&g_pool[((size_t)bb * 768 + n0 + c) * 3 + k], red[e]);
    }
}

// ------------------------------ small kernels ------------------------------
// fp32 -> fp16 copy for Xp (4 elems/thread).
__global__ __launch_bounds__(256) void cvt_xp_kernel(const float* __restrict__ in){
    int i = blockIdx.x * 256 + threadIdx.x;
    if (i >= 2621440) return;
    float4 v = *(const float4*)(in + (size_t)i * 4);
    __half2 a = __floats2half2_rn(v.x, v.y);
    __half2 b = __floats2half2_rn(v.z, v.w);
    uint2 u; u.x = *(uint32_t*)&a; u.y = *(uint32_t*)&b;
    *(uint2*)(g_XpH + (size_t)i * 4) = u;
}
__global__ __launch_bounds__(256) void cvt_w2_kernel(const float* __restrict__ in){
    int i = blockIdx.x * 256 + threadIdx.x;
    if (i >= 61440) return;
    float4 v = *(const float4*)(in + (size_t)i * 4);
    __half2 a = __floats2half2_rn(v.x, v.y);
    __half2 b = __floats2half2_rn(v.z, v.w);
    uint2 u; u.x = *(uint32_t*)&a; u.y = *(uint32_t*)&b;
    *(uint2*)(g_W2H + (size_t)i * 4) = u;
}

// Xe + W1 + Wc conversion + pool init, one grid.
// ranges (in 256-thread block units):
//   [0, 24576)        : Xe float4 units (6291456)
//   [24576, 25152)    : W1 float4 units (147456)
//   [25152, 27456)    : Wc idx (589824)
//   [27456, 28032)    : pool init (147456)
__global__ __launch_bounds__(256) void prep_main_kernel(
    const float* __restrict__ Xe, const float* __restrict__ W1,
    const float* __restrict__ Wc)
{
    int blk = blockIdx.x;
    int t   = threadIdx.x;
    if (blk < 24576){
        int i = blk * 256 + t;
        float4 v = *(const float4*)(Xe + (size_t)i * 4);
        __half2 a = __floats2half2_rn(v.x, v.y);
        __half2 b = __floats2half2_rn(v.z, v.w);
        uint2 u; u.x = *(uint32_t*)&a; u.y = *(uint32_t*)&b;
        *(uint2*)(g_XeH + (size_t)i * 4) = u;
    } else if (blk < 25152){
        int i = (blk - 24576) * 256 + t;
        float4 v = *(const float4*)(W1 + (size_t)i * 4);
        __half2 a = __floats2half2_rn(v.x, v.y);
        __half2 b = __floats2half2_rn(v.z, v.w);
        uint2 u; u.x = *(uint32_t*)&a; u.y = *(uint32_t*)&b;
        *(uint2*)(g_W1H + (size_t)i * 4) = u;
    } else if (blk < 27456){
        int idx = (blk - 25152) * 256 + t;
        const float* src = Wc + (size_t)idx * 3;
        #pragma unroll
        for (int tp = 0; tp < 3; tp++)
            g_WcH[(size_t)tp * 589824 + idx] = __float2half_rn(src[tp]);
    } else {
        int i = (blk - 27456) * 256 + t;
        g_pool[i] = 0.f;
    }
}

__global__ void final_kernel(float* __restrict__ out){
    int i = blockIdx.x * 256 + threadIdx.x;
    if (i < 147456) out[i] = tanhf(g_pool[i]);
}

// ---------------------------------------------------------------------------
extern "C" void kernel_launch(void* const* d_in, const int* in_sizes, int n_in,
                              void* d_out, int out_size)
{
    const float* Xp = (const float*)d_in[0];
    const float* Xe = (const float*)d_in[1];
    const int*   Xm = (const int*)  d_in[2];
    const float* W1 = (const float*)d_in[3];
    const float* b1 = (const float*)d_in[4];
    const float* W2 = (const float*)d_in[5];
    const float* b2 = (const float*)d_in[6];
    const float* Wc = (const float*)d_in[7];
    const float* bc = (const float*)d_in[8];
    float* out = (float*)d_out;

    cudaFuncSetAttribute(gemm_p_kernel, cudaFuncAttributeMaxDynamicSharedMemorySize, SMEM_BYTES);
    cudaFuncSetAttribute(gemm_e_kernel, cudaFuncAttributeMaxDynamicSharedMemorySize, SMEM_BYTES);
    cudaFuncSetAttribute(gemm_c_kernel, cudaFuncAttributeMaxDynamicSharedMemorySize, SMEM_BYTES);

    // launch order chosen so ncu (-s 5 -c 1) captures gemm_c_kernel (launch #6)
    cvt_xp_kernel<<<10240, 256>>>(Xp);                 // 1
    cvt_w2_kernel<<<240, 256>>>(W2);                   // 2
    prep_main_kernel<<<28032, 256>>>(Xe, W1, Wc);      // 3

    dim3 gg(6, 256);   // 6 N-tiles x 256 M-tiles
    gemm_p_kernel<<<gg, 256, SMEM_BYTES>>>(b2);        // 4
    gemm_e_kernel<<<gg, 256, SMEM_BYTES>>>(Xe, b1);    // 5
    gemm_c_kernel<<<gg, 256, SMEM_BYTES>>>(Xm, bc);    // 6  <- ncu capture
    final_kernel<<<576, 256>>>(out);                   // 7
}